// round 4
// baseline (speedup 1.0000x reference)
#include <cuda_runtime.h>

// Problem constants
#define H 512
#define W 512
#define HW (H * W)
#define NC 48              // 16 batch * 3 channels
#define OH 171
#define OW 171
#define NBANDS 86          // 2 output rows per band (last band has 1)
#define NBLOCKS (NC * NBANDS)    // 4128
#define TOTAL (NC * OH * OW)     // 1,403,568

// smem row stride: 516 floats. Data col j lives at +4+j (j=0..511), a zero
// pad sits at +3 so reading col -1 (left edge) yields 0. float4 stores at
// +4+4q stay 16B aligned (516 % 4 == 0).
#define RS 516

__device__ float        g_partial = 0.0f;
__device__ unsigned int g_count   = 0;

__global__ void __launch_bounds__(256) ssim_kernel(
    const float* __restrict__ img1,
    const float* __restrict__ img2,
    const float* __restrict__ window,
    float* __restrict__ out)
{
    const float C1 = 0.0001f;   // 0.01^2
    const float C2 = 0.0009f;   // 0.03^2

    __shared__ float sm[2][6][RS];
    __shared__ float wsum[8];

    const int tid   = threadIdx.x;
    const int band  = blockIdx.x % NBANDS;
    const int plane = blockIdx.x / NBANDS;
    const int row0  = 6 * band - 1;             // first input row of band
    const int npix  = (band == NBANDS - 1) ? OW : 2 * OW;

    // 3x3 gaussian window (identical per channel)
    float w[9];
    #pragma unroll
    for (int i = 0; i < 9; i++) w[i] = __ldg(window + i);

    // zero slot at col -1 of each of the 12 smem rows
    if (tid < 12) sm[tid / 6][tid % 6][3] = 0.0f;

    // ---- load phase: 6 coalesced float4 per thread, front-batched ----
    // k in [0,3): img1, k in [3,6): img2. Each image: 6 rows x 128 float4.
    #pragma unroll
    for (int k = 0; k < 6; k++) {
        const float* __restrict__ base = (k < 3) ? img1 : img2;
        const int rem = tid + (k % 3) * 256;    // 0..767 within image
        const int r   = rem >> 7;               // row 0..5
        const int q   = rem & 127;              // float4 index within row
        const int rg  = row0 + r;

        float4 v = make_float4(0.f, 0.f, 0.f, 0.f);
        if (rg >= 0 && rg < H)
            v = __ldg((const float4*)(base + (size_t)plane * HW + rg * W + 4 * q));
        *(float4*)&sm[k / 3][r][4 + 4 * q] = v;
    }
    __syncthreads();

    // ---- compute phase: up to 2 pixels per thread from smem ----
    float acc = 0.0f;
    #pragma unroll
    for (int pp = 0; pp < 2; pp++) {
        const int p = tid + pp * 256;
        if (p < npix) {
            int oyl, ox;
            if (p < OW) { oyl = 0; ox = p; }
            else        { oyl = 1; ox = p - OW; }

            float m1 = 0.f, m2 = 0.f, s11 = 0.f, s22 = 0.f, s12 = 0.f;
            #pragma unroll
            for (int r = 0; r < 3; r++) {
                // data col (3*ox-1+c) -> smem offset 4 + 3*ox - 1 + c = 3 + 3*ox + c
                const float* __restrict__ r1 = &sm[0][3 * oyl + r][3 + 3 * ox];
                const float* __restrict__ r2 = &sm[1][3 * oyl + r][3 + 3 * ox];
                #pragma unroll
                for (int c = 0; c < 3; c++) {
                    const float wt = w[r * 3 + c];
                    const float a  = r1[c];
                    const float b  = r2[c];
                    const float wa = wt * a;
                    const float wb = wt * b;
                    m1  += wa;
                    m2  += wb;
                    s11 = fmaf(wa, a, s11);
                    s22 = fmaf(wb, b, s22);
                    s12 = fmaf(wa, b, s12);
                }
            }

            const float a11 = m1 * m1;
            const float a22 = m2 * m2;
            const float a12 = m1 * m2;
            const float v1  = s11 - a11;
            const float v2  = s22 - a22;
            const float v12 = s12 - a12;
            const float num = (2.0f * a12 + C1) * (2.0f * v12 + C2);
            const float den = (a11 + a22 + C1) * (v1 + v2 + C2);
            acc += num / den;
        }
    }

    // ---- block reduction ----
    #pragma unroll
    for (int o = 16; o > 0; o >>= 1)
        acc += __shfl_down_sync(0xffffffffu, acc, o);

    const int lane = tid & 31;
    const int wid  = tid >> 5;
    if (lane == 0) wsum[wid] = acc;
    __syncthreads();

    if (wid == 0) {
        acc = (lane < 8) ? wsum[lane] : 0.0f;
        #pragma unroll
        for (int o = 4; o > 0; o >>= 1)
            acc += __shfl_down_sync(0xffffffffu, acc, o);
        if (lane == 0)
            atomicAdd(&g_partial, acc * (1.0f / (float)TOTAL));
    }

    // ---- last block publishes result, resets scratch (graph-replay safe) ----
    __shared__ bool is_last;
    if (tid == 0) {
        __threadfence();
        const unsigned prev = atomicAdd(&g_count, 1u);
        is_last = (prev == (unsigned)(gridDim.x - 1));
    }
    __syncthreads();
    if (is_last && tid == 0) {
        *out      = g_partial;
        g_partial = 0.0f;
        g_count   = 0;
    }
}

extern "C" void kernel_launch(void* const* d_in, const int* in_sizes, int n_in,
                              void* d_out, int out_size)
{
    const float* img1   = (const float*)d_in[0];
    const float* img2   = (const float*)d_in[1];
    const float* window = (const float*)d_in[2];
    float* out = (float*)d_out;

    ssim_kernel<<<NBLOCKS, 256>>>(img1, img2, window, out);
}

// round 5
// speedup vs baseline: 1.0151x; 1.0151x over previous
#include <cuda_runtime.h>
#include <cstdint>

// Problem constants
#define H 512
#define W 512
#define HW (H * W)
#define NC 48                 // 16 batch * 3 channels
#define OH 171
#define OW 171
#define NTASKS (NC * OH)      // 8208 one-output-row tasks
#define NBLOCKS 1184          // 148 SMs * 8 blocks — single persistent wave
#define TOTAL (NC * OH * OW)  // 1,403,568

// smem row stride: 516 floats. Data col j at +4+j; zero pad at +3 serves as
// col -1 (left edge). cp.async dsts at +4+4q stay 16B aligned (516 % 4 == 0).
#define RS 516

__device__ float        g_partial = 0.0f;
__device__ unsigned int g_count   = 0;

__device__ __forceinline__ void cp16(uint32_t dst_smem, const void* src, int src_size) {
    asm volatile("cp.async.cg.shared.global [%0], [%1], 16, %2;\n"
                 :: "r"(dst_smem), "l"(src), "r"(src_size));
}
__device__ __forceinline__ void cp_commit() {
    asm volatile("cp.async.commit_group;\n" ::);
}
__device__ __forceinline__ void cp_wait_1() {
    asm volatile("cp.async.wait_group 1;\n" ::);
}
__device__ __forceinline__ void cp_wait_0() {
    asm volatile("cp.async.wait_group 0;\n" ::);
}

__global__ void __launch_bounds__(256) ssim_kernel(
    const float* __restrict__ img1,
    const float* __restrict__ img2,
    const float* __restrict__ window,
    float* __restrict__ out)
{
    const float C1 = 0.0001f;   // 0.01^2
    const float C2 = 0.0009f;   // 0.03^2

    __shared__ float sm[2][2][3][RS];   // [stage][image][row][cols]
    __shared__ float wsum[8];

    const int tid = threadIdx.x;

    // 3x3 gaussian window (identical per channel)
    float w[9];
    #pragma unroll
    for (int i = 0; i < 9; i++) w[i] = __ldg(window + i);

    // zero slots at col -1 (smem offset 3) — never overwritten by cp.async
    if (tid < 12) {
        const int s  = tid / 6;
        const int im = (tid % 6) / 3;
        const int r  = tid % 3;
        sm[s][im][r][3] = 0.0f;
    }

    // Per-thread load slots: 2 img x 3 rows x 128 float4 = 768 -> 3 per thread
    int l_im[3], l_r[3], l_q[3];
    uint32_t l_dst[2][3];
    #pragma unroll
    for (int j = 0; j < 3; j++) {
        const int idx = tid + 256 * j;      // 0..767
        l_im[j] = idx / 384;
        const int rem = idx % 384;
        l_r[j] = rem >> 7;                  // 0..2
        l_q[j] = rem & 127;                 // float4 index 0..127
        l_dst[0][j] = (uint32_t)__cvta_generic_to_shared(&sm[0][l_im[j]][l_r[j]][4 + 4 * l_q[j]]);
        l_dst[1][j] = (uint32_t)__cvta_generic_to_shared(&sm[1][l_im[j]][l_r[j]][4 + 4 * l_q[j]]);
    }

    const float* const imgs[2] = { img1, img2 };

    // prefetch one task into stage s
    auto prefetch = [&](int task, int s) {
        const int plane = task / OH;
        const int oy    = task % OH;
        const size_t pbase = (size_t)plane * HW;
        #pragma unroll
        for (int j = 0; j < 3; j++) {
            const int row = 3 * oy - 1 + l_r[j];          // -1..511
            const float* src = imgs[l_im[j]] + pbase + row * W + 4 * l_q[j];
            const int size = (row >= 0) ? 16 : 0;         // hw zero-fill for pad row
            cp16(l_dst[s][j], src, size);
        }
        cp_commit();
    };

    float acc = 0.0f;

    int task = blockIdx.x;
    if (task < NTASKS) prefetch(task, 0);

    int i = 0;
    for (; task < NTASKS; task += NBLOCKS, i++) {
        const int s    = i & 1;
        const int next = task + NBLOCKS;
        const bool have_next = (next < NTASKS);

        if (have_next) { prefetch(next, s ^ 1); cp_wait_1(); }
        else           { cp_wait_0(); }
        __syncthreads();                     // stage s data visible to all

        if (tid < OW) {
            const int ox = tid;
            float m1 = 0.f, m2 = 0.f, s11 = 0.f, s22 = 0.f, s12 = 0.f;
            #pragma unroll
            for (int r = 0; r < 3; r++) {
                const float* __restrict__ r1 = &sm[s][0][r][3 + 3 * ox];
                const float* __restrict__ r2 = &sm[s][1][r][3 + 3 * ox];
                #pragma unroll
                for (int c = 0; c < 3; c++) {
                    const float wt = w[r * 3 + c];
                    const float a  = r1[c];
                    const float b  = r2[c];
                    const float wa = wt * a;
                    const float wb = wt * b;
                    m1  += wa;
                    m2  += wb;
                    s11 = fmaf(wa, a, s11);
                    s22 = fmaf(wb, b, s22);
                    s12 = fmaf(wa, b, s12);
                }
            }
            const float a11 = m1 * m1;
            const float a22 = m2 * m2;
            const float a12 = m1 * m2;
            const float v1  = s11 - a11;
            const float v2  = s22 - a22;
            const float v12 = s12 - a12;
            const float num = (2.0f * a12 + C1) * (2.0f * v12 + C2);
            const float den = (a11 + a22 + C1) * (v1 + v2 + C2);
            acc += num / den;
        }
        __syncthreads();                     // reads of stage s done before overwrite
    }

    // ---- block reduction ----
    #pragma unroll
    for (int o = 16; o > 0; o >>= 1)
        acc += __shfl_down_sync(0xffffffffu, acc, o);

    const int lane = tid & 31;
    const int wid  = tid >> 5;
    if (lane == 0) wsum[wid] = acc;
    __syncthreads();

    if (wid == 0) {
        acc = (lane < 8) ? wsum[lane] : 0.0f;
        #pragma unroll
        for (int o = 4; o > 0; o >>= 1)
            acc += __shfl_down_sync(0xffffffffu, acc, o);
        if (lane == 0)
            atomicAdd(&g_partial, acc * (1.0f / (float)TOTAL));
    }

    // ---- last block publishes result, resets scratch (graph-replay safe) ----
    __shared__ bool is_last;
    if (tid == 0) {
        __threadfence();
        const unsigned prev = atomicAdd(&g_count, 1u);
        is_last = (prev == (unsigned)(gridDim.x - 1));
    }
    __syncthreads();
    if (is_last && tid == 0) {
        *out      = g_partial;
        g_partial = 0.0f;
        g_count   = 0;
    }
}

extern "C" void kernel_launch(void* const* d_in, const int* in_sizes, int n_in,
                              void* d_out, int out_size)
{
    const float* img1   = (const float*)d_in[0];
    const float* img2   = (const float*)d_in[1];
    const float* window = (const float*)d_in[2];
    float* out = (float*)d_out;

    ssim_kernel<<<NBLOCKS, 256>>>(img1, img2, window, out);
}

// round 6
// speedup vs baseline: 1.2579x; 1.2393x over previous
#include <cuda_runtime.h>

// Problem constants
#define H 512
#define W 512
#define HW (H * W)
#define NC 48                 // 16 batch * 3 channels
#define OH 171
#define OW 171
#define TOTAL (NC * OH * OW)  // 1,403,568 output pixels
#define NBLOCKS 888           // 148 SMs * 6 resident blocks — one clean wave

__device__ float        g_partial = 0.0f;
__device__ unsigned int g_count   = 0;

__global__ void __launch_bounds__(256, 6) ssim_kernel(
    const float* __restrict__ img1,
    const float* __restrict__ img2,
    const float* __restrict__ window,
    float* __restrict__ out)
{
    const float C1 = 0.0001f;   // 0.01^2
    const float C2 = 0.0009f;   // 0.03^2

    // 3x3 gaussian window (identical per channel) — broadcast, L1-resident
    float w[9];
    #pragma unroll
    for (int i = 0; i < 9; i++) w[i] = __ldg(window + i);

    float acc = 0.0f;

    const int stride = NBLOCKS * 256;
    for (int idx = blockIdx.x * blockDim.x + threadIdx.x; idx < TOTAL; idx += stride) {
        const int ox    = idx % OW;
        const int t     = idx / OW;
        const int oy    = t % OH;
        const int plane = t / OH;

        const float* __restrict__ p1 = img1 + (size_t)plane * HW;
        const float* __restrict__ p2 = img2 + (size_t)plane * HW;

        const int ix = 3 * ox - 1;
        const int iy = 3 * oy - 1;

        float a[9], b[9];

        if (ix >= 0 && iy >= 0) {
            // Interior fast path (~98.8% of pixels). High side always in
            // bounds (3*170+1 = 511). Batch all 18 loads before computing.
            const float* __restrict__ q1 = p1 + iy * W + ix;
            const float* __restrict__ q2 = p2 + iy * W + ix;
            #pragma unroll
            for (int r = 0; r < 3; r++)
                #pragma unroll
                for (int c = 0; c < 3; c++)
                    a[r * 3 + c] = __ldg(q1 + r * W + c);
            #pragma unroll
            for (int r = 0; r < 3; r++)
                #pragma unroll
                for (int c = 0; c < 3; c++)
                    b[r * 3 + c] = __ldg(q2 + r * W + c);
        } else {
            // Boundary: only index -1 can occur (zero padding)
            #pragma unroll
            for (int r = 0; r < 3; r++) {
                #pragma unroll
                for (int c = 0; c < 3; c++) {
                    const int row = iy + r;
                    const int col = ix + c;
                    const bool ok = (row >= 0) && (col >= 0);
                    a[r * 3 + c] = ok ? __ldg(p1 + row * W + col) : 0.0f;
                    b[r * 3 + c] = ok ? __ldg(p2 + row * W + col) : 0.0f;
                }
            }
        }

        float mu1 = 0.f, mu2 = 0.f, s11 = 0.f, s22 = 0.f, s12 = 0.f;
        #pragma unroll
        for (int k = 0; k < 9; k++) {
            const float wa = w[k] * a[k];
            const float wb = w[k] * b[k];
            mu1 += wa;
            mu2 += wb;
            s11 = fmaf(wa, a[k], s11);
            s22 = fmaf(wb, b[k], s22);
            s12 = fmaf(wa, b[k], s12);
        }

        const float m11 = mu1 * mu1;
        const float m22 = mu2 * mu2;
        const float m12 = mu1 * mu2;
        const float v1  = s11 - m11;   // sigma1_sq
        const float v2  = s22 - m22;   // sigma2_sq
        const float v12 = s12 - m12;   // sigma12

        const float num = (2.0f * m12 + C1) * (2.0f * v12 + C2);
        const float den = (m11 + m22 + C1) * (v1 + v2 + C2);
        acc += __fdividef(num, den);
    }

    // ---- block reduction: warp shuffle -> smem -> warp0 -> one atomic ----
    #pragma unroll
    for (int o = 16; o > 0; o >>= 1)
        acc += __shfl_down_sync(0xffffffffu, acc, o);

    __shared__ float wsum[8];
    const int lane = threadIdx.x & 31;
    const int wid  = threadIdx.x >> 5;
    if (lane == 0) wsum[wid] = acc;
    __syncthreads();

    if (wid == 0) {
        acc = (lane < 8) ? wsum[lane] : 0.0f;
        #pragma unroll
        for (int o = 4; o > 0; o >>= 1)
            acc += __shfl_down_sync(0xffffffffu, acc, o);
        if (lane == 0)
            atomicAdd(&g_partial, acc * (1.0f / (float)TOTAL));
    }

    // ---- last block publishes result, resets scratch (graph-replay safe) ----
    __shared__ bool is_last;
    if (threadIdx.x == 0) {
        __threadfence();
        const unsigned prev = atomicAdd(&g_count, 1u);
        is_last = (prev == (unsigned)(gridDim.x - 1));
    }
    __syncthreads();
    if (is_last && threadIdx.x == 0) {
        *out      = g_partial;
        g_partial = 0.0f;
        g_count   = 0;
    }
}

extern "C" void kernel_launch(void* const* d_in, const int* in_sizes, int n_in,
                              void* d_out, int out_size)
{
    const float* img1   = (const float*)d_in[0];
    const float* img2   = (const float*)d_in[1];
    const float* window = (const float*)d_in[2];
    float* out = (float*)d_out;

    ssim_kernel<<<NBLOCKS, 256>>>(img1, img2, window, out);
}